// round 1
// baseline (speedup 1.0000x reference)
#include <cuda_runtime.h>
#include <cstdint>

// ---------------------------------------------------------------------------
// GraphSAGE: 3x SAGEConv(mean) + linear head.
// N=100000 nodes, E=3200000 edges, dims 64 -> 64 -> 32 -> 16 -> 1
//
// Restructuring: mean-agg is linear, so  agg(x)@Wl == segsum((x@Wl)[src])/cnt.
// Per layer: t = x@Wl ; u = x@Wr + b ; s[dst] += t[src] (red.v4.f32) ;
//            h = relu(s * inv_deg + u)
// Degree (cnt) computed once, reused for all layers.
// ---------------------------------------------------------------------------

#define N_NODES 100000
#define IN_CH   64

// Scratch (device globals; allocation is forbidden)
__device__ float g_t[(size_t)N_NODES * 64];
__device__ float g_u[(size_t)N_NODES * 64];
__device__ float g_s[(size_t)N_NODES * 64];
__device__ float g_h[(size_t)N_NODES * 64];
__device__ float g_deg[N_NODES];

// ---------------- degree ----------------
__global__ void zero_deg_kernel(float* __restrict__ deg, int n) {
    int i = blockIdx.x * blockDim.x + threadIdx.x;
    if (i < n) deg[i] = 0.0f;
}

__global__ void count_kernel(const int* __restrict__ dst, float* __restrict__ deg, int e) {
    int i = blockIdx.x * blockDim.x + threadIdx.x;
    if (i < e) atomicAdd(&deg[dst[i]], 1.0f);
}

__global__ void invert_deg_kernel(float* __restrict__ deg, int n) {
    int i = blockIdx.x * blockDim.x + threadIdx.x;
    if (i < n) deg[i] = 1.0f / fmaxf(deg[i], 1.0f);
}

// ---------------- fused dual GEMM: t = X@Wl, u = X@Wr + b, s = 0 ----------------
template <int DIN, int DOUT>
__global__ void __launch_bounds__(128)
gemm_kernel(const float* __restrict__ X,
            const float* __restrict__ Wl, const float* __restrict__ Wr,
            const float* __restrict__ B,
            float* __restrict__ T, float* __restrict__ U, float* __restrict__ S,
            int n) {
    __shared__ float sWl[DIN * DOUT];
    __shared__ float sWr[DIN * DOUT];
    __shared__ float sB[DOUT];

    for (int i = threadIdx.x; i < DIN * DOUT; i += blockDim.x) {
        sWl[i] = Wl[i];
        sWr[i] = Wr[i];
    }
    if (threadIdx.x < DOUT) sB[threadIdx.x] = B[threadIdx.x];
    __syncthreads();

    int node = blockIdx.x * blockDim.x + threadIdx.x;
    if (node >= n) return;

    // x row into registers (float4 loads)
    float xr[DIN];
    const float4* xp = reinterpret_cast<const float4*>(X + (size_t)node * DIN);
#pragma unroll
    for (int k4 = 0; k4 < DIN / 4; k4++) {
        float4 v = xp[k4];
        xr[4 * k4 + 0] = v.x; xr[4 * k4 + 1] = v.y;
        xr[4 * k4 + 2] = v.z; xr[4 * k4 + 3] = v.w;
    }

    constexpr int JT = (DOUT >= 16) ? 16 : DOUT;
    float* tp = T + (size_t)node * DOUT;
    float* up = U + (size_t)node * DOUT;
    float* sp = S + (size_t)node * DOUT;

    for (int j0 = 0; j0 < DOUT; j0 += JT) {
        float accL[JT], accR[JT];
#pragma unroll
        for (int j = 0; j < JT; j++) {
            accL[j] = 0.0f;
            accR[j] = sB[j0 + j];
        }
#pragma unroll
        for (int k = 0; k < DIN; k++) {
            float xk = xr[k];
#pragma unroll
            for (int j = 0; j < JT; j++) {
                accL[j] = fmaf(xk, sWl[k * DOUT + j0 + j], accL[j]);
                accR[j] = fmaf(xk, sWr[k * DOUT + j0 + j], accR[j]);
            }
        }
#pragma unroll
        for (int j = 0; j < JT; j += 4) {
            *reinterpret_cast<float4*>(tp + j0 + j) =
                make_float4(accL[j], accL[j + 1], accL[j + 2], accL[j + 3]);
            *reinterpret_cast<float4*>(up + j0 + j) =
                make_float4(accR[j], accR[j + 1], accR[j + 2], accR[j + 3]);
            *reinterpret_cast<float4*>(sp + j0 + j) = make_float4(0.f, 0.f, 0.f, 0.f);
        }
    }
}

// ---------------- scatter: s[dst] += t[src], vectorized f32x4 reductions ----------------
template <int DOUT>
__global__ void __launch_bounds__(256)
scatter_kernel(const int* __restrict__ src, const int* __restrict__ dst,
               const float* __restrict__ T, float* __restrict__ S, int e) {
    constexpr int C = DOUT / 4;                       // float4 chunks per edge
    constexpr int LOG = (C == 16) ? 4 : (C == 8) ? 3 : 2;
    unsigned idx = blockIdx.x * blockDim.x + threadIdx.x;
    unsigned total = (unsigned)e * C;
    if (idx >= total) return;
    int ei = (int)(idx >> LOG);
    int c  = (int)(idx & (C - 1));

    int sn = __ldg(src + ei);
    int dn = __ldg(dst + ei);

    float4 v = __ldg(reinterpret_cast<const float4*>(T + (size_t)sn * DOUT) + c);
    float* p = S + (size_t)dn * DOUT + 4 * c;
    asm volatile("red.global.add.v4.f32 [%0], {%1, %2, %3, %4};"
                 :: "l"(p), "f"(v.x), "f"(v.y), "f"(v.z), "f"(v.w)
                 : "memory");
}

// ---------------- combine: h = relu(s * inv_deg + u) ----------------
template <int DOUT>
__global__ void __launch_bounds__(256)
combine_kernel(const float* __restrict__ S, const float* __restrict__ U,
               const float* __restrict__ deg, float* __restrict__ H, int n) {
    constexpr int C = DOUT / 4;
    int idx = blockIdx.x * blockDim.x + threadIdx.x;
    if (idx >= n * C) return;
    int node = idx / C;
    float inv = __ldg(deg + node);
    float4 s = __ldg(reinterpret_cast<const float4*>(S) + idx);
    float4 u = __ldg(reinterpret_cast<const float4*>(U) + idx);
    float4 h;
    h.x = fmaxf(fmaf(s.x, inv, u.x), 0.0f);
    h.y = fmaxf(fmaf(s.y, inv, u.y), 0.0f);
    h.z = fmaxf(fmaf(s.z, inv, u.z), 0.0f);
    h.w = fmaxf(fmaf(s.w, inv, u.w), 0.0f);
    reinterpret_cast<float4*>(H)[idx] = h;
}

// ---------------- head: out = h @ Wc + bc  (16 -> 1) ----------------
__global__ void __launch_bounds__(256)
head_kernel(const float* __restrict__ H, const float* __restrict__ Wc,
            const float* __restrict__ bc, float* __restrict__ out, int n) {
    int node = blockIdx.x * blockDim.x + threadIdx.x;
    if (node >= n) return;
    const float4* hp = reinterpret_cast<const float4*>(H + (size_t)node * 16);
    float acc = __ldg(bc);
#pragma unroll
    for (int c = 0; c < 4; c++) {
        float4 h = hp[c];
        acc = fmaf(h.x, __ldg(Wc + 4 * c + 0), acc);
        acc = fmaf(h.y, __ldg(Wc + 4 * c + 1), acc);
        acc = fmaf(h.z, __ldg(Wc + 4 * c + 2), acc);
        acc = fmaf(h.w, __ldg(Wc + 4 * c + 3), acc);
    }
    out[node] = acc;
}

// ---------------------------------------------------------------------------

static inline int cdiv(long long a, int b) { return (int)((a + b - 1) / b); }

template <int DIN, int DOUT>
static void run_layer(const float* X, const float* Wl, const float* Wr, const float* B,
                      const int* src, const int* dst,
                      float* t, float* u, float* s, float* h, const float* deg,
                      int n, int e) {
    gemm_kernel<DIN, DOUT><<<cdiv(n, 128), 128>>>(X, Wl, Wr, B, t, u, s, n);
    long long items = (long long)e * (DOUT / 4);
    scatter_kernel<DOUT><<<cdiv(items, 256), 256>>>(src, dst, t, s, e);
    combine_kernel<DOUT><<<cdiv((long long)n * (DOUT / 4), 256), 256>>>(s, u, deg, h, n);
}

extern "C" void kernel_launch(void* const* d_in, const int* in_sizes, int n_in,
                              void* d_out, int out_size) {
    const float* x   = (const float*)d_in[0];
    const int* eidx  = (const int*)d_in[1];
    const float* Wl0 = (const float*)d_in[2];
    const float* Wr0 = (const float*)d_in[3];
    const float* b0  = (const float*)d_in[4];
    const float* Wl1 = (const float*)d_in[5];
    const float* Wr1 = (const float*)d_in[6];
    const float* b1  = (const float*)d_in[7];
    const float* Wl2 = (const float*)d_in[8];
    const float* Wr2 = (const float*)d_in[9];
    const float* b2  = (const float*)d_in[10];
    const float* Wc  = (const float*)d_in[11];
    const float* bc  = (const float*)d_in[12];
    float* out = (float*)d_out;

    const int n = in_sizes[0] / IN_CH;      // 100000
    const int e = in_sizes[1] / 2;          // 3200000
    const int* src = eidx;
    const int* dst = eidx + e;

    float *t, *u, *s, *h, *deg;
    cudaGetSymbolAddress((void**)&t, g_t);
    cudaGetSymbolAddress((void**)&u, g_u);
    cudaGetSymbolAddress((void**)&s, g_s);
    cudaGetSymbolAddress((void**)&h, g_h);
    cudaGetSymbolAddress((void**)&deg, g_deg);

    // degree (once, reused for all 3 layers)
    zero_deg_kernel<<<cdiv(n, 256), 256>>>(deg, n);
    count_kernel<<<cdiv(e, 256), 256>>>(dst, deg, e);
    invert_deg_kernel<<<cdiv(n, 256), 256>>>(deg, n);

    run_layer<64, 64>(x, Wl0, Wr0, b0, src, dst, t, u, s, h, deg, n, e);
    run_layer<64, 32>(h, Wl1, Wr1, b1, src, dst, t, u, s, h, deg, n, e);
    run_layer<32, 16>(h, Wl2, Wr2, b2, src, dst, t, u, s, h, deg, n, e);

    head_kernel<<<cdiv(n, 256), 256>>>(h, Wc, bc, out, n);
}

// round 2
// speedup vs baseline: 1.1754x; 1.1754x over previous
#include <cuda_runtime.h>
#include <cstdint>

// ---------------------------------------------------------------------------
// GraphSAGE: 3x SAGEConv(mean) + linear head.
// N=100000, E=3200000, dims 64 -> 64 -> 32 -> 16 -> 1
//
// v2: CSR gather (no atomics in aggregation) + warp-per-node FFMA2 GEMM.
// Per layer: t = x@Wl, u = x@Wr + b  (fused dual GEMM, f32x2 packed math)
//            h[n] = relu( (sum_{e: dst=n} t[src_e]) * inv_deg[n] + u[n] )
// CSR (row_start, csr_src) + inv_deg built once per launch, reused 3x.
// ---------------------------------------------------------------------------

#define N_NODES 100000
#define MAX_E   3200000

// Scratch (device globals; allocation is forbidden)
__device__ float g_t[(size_t)N_NODES * 64];
__device__ float g_u[(size_t)N_NODES * 64];
__device__ float g_h[(size_t)N_NODES * 64];
__device__ float g_inv[N_NODES];
__device__ int   g_cnt[N_NODES];
__device__ int   g_rs[N_NODES + 1];
__device__ int   g_cur[N_NODES];
__device__ int   g_csr[MAX_E];
__device__ int   g_bsum[512];

static inline int cdiv(long long a, int b) { return (int)((a + b - 1) / b); }

// ---------------- CSR build ----------------
__global__ void zero_cnt_kernel(int* __restrict__ cnt, int n) {
    int i = blockIdx.x * blockDim.x + threadIdx.x;
    if (i < n) cnt[i] = 0;
}

__global__ void hist_kernel(const int* __restrict__ dst, int* __restrict__ cnt, int e) {
    int i = blockIdx.x * blockDim.x + threadIdx.x;
    if (i < e) atomicAdd(&cnt[dst[i]], 1);
}

// block-local exclusive scan -> rs[i]; block total -> bsum[b]
__global__ void __launch_bounds__(256)
scan1_kernel(const int* __restrict__ cnt, int* __restrict__ rs,
             int* __restrict__ bsum, int n) {
    __shared__ int sm[256];
    int tid = threadIdx.x;
    int gi = blockIdx.x * 256 + tid;
    int v = (gi < n) ? cnt[gi] : 0;
    sm[tid] = v;
    __syncthreads();
#pragma unroll
    for (int off = 1; off < 256; off <<= 1) {
        int t = (tid >= off) ? sm[tid - off] : 0;
        __syncthreads();
        sm[tid] += t;
        __syncthreads();
    }
    if (gi < n) rs[gi] = sm[tid] - v;         // local exclusive
    if (tid == 255) bsum[blockIdx.x] = sm[255];
}

// single block: exclusive scan of block sums (nb <= 512)
__global__ void __launch_bounds__(512)
scan2_kernel(int* __restrict__ bsum, int nb) {
    __shared__ int sm[512];
    int tid = threadIdx.x;
    int v = (tid < nb) ? bsum[tid] : 0;
    sm[tid] = v;
    __syncthreads();
#pragma unroll
    for (int off = 1; off < 512; off <<= 1) {
        int t = (tid >= off) ? sm[tid - off] : 0;
        __syncthreads();
        sm[tid] += t;
        __syncthreads();
    }
    if (tid < nb) bsum[tid] = sm[tid] - v;    // exclusive
}

// finalize: global row_start, cursor copy, inv_deg, rs[n] = E
__global__ void scan3_kernel(const int* __restrict__ cnt, int* __restrict__ rs,
                             int* __restrict__ cur, float* __restrict__ inv,
                             const int* __restrict__ bsum, int n) {
    int gi = blockIdx.x * blockDim.x + threadIdx.x;
    if (gi >= n) return;
    int rsv = rs[gi] + bsum[blockIdx.x];
    rs[gi] = rsv;
    cur[gi] = rsv;
    int c = cnt[gi];
    inv[gi] = 1.0f / fmaxf((float)c, 1.0f);
    if (gi == n - 1) rs[n] = rsv + c;
}

__global__ void fill_kernel(const int* __restrict__ src, const int* __restrict__ dst,
                            int* __restrict__ cur, int* __restrict__ csr, int e) {
    int i = blockIdx.x * blockDim.x + threadIdx.x;
    if (i < e) {
        int p = atomicAdd(&cur[dst[i]], 1);
        csr[p] = src[i];
    }
}

// ---------------- dual GEMM: t = X@Wl, u = X@Wr + b  (warp-per-node, f32x2) --
// Lanes split DOUT columns in pairs; W = DOUT/2 lanes serve one node, so a
// warp handles NPW = 32/W nodes. x loaded coalesced, broadcast via shfl.
// Wl/Wr interleaved in smem: sWc[k][pair] = {Wl[k][2p],Wl[k][2p+1],Wr[k][2p],Wr[k][2p+1]}
template <int DIN, int DOUT>
__global__ void __launch_bounds__(256)
gemm_kernel(const float* __restrict__ X,
            const float* __restrict__ Wl, const float* __restrict__ Wr,
            const float* __restrict__ B,
            float* __restrict__ T, float* __restrict__ U, int n) {
    constexpr int W   = DOUT / 2;   // lanes per node (32/16/8)
    constexpr int NPW = 32 / W;     // nodes per warp  (1/2/4)
    constexpr int NX  = DIN / W;    // x regs per lane

    __shared__ float sWc[DIN * 2 * DOUT];
    __shared__ float sB[DOUT];

    for (int i = threadIdx.x; i < DIN * DOUT; i += blockDim.x) {
        int k = i / DOUT, j = i % DOUT;
        sWc[k * 2 * DOUT + (j >> 1) * 4 + (j & 1)]     = Wl[i];
        sWc[k * 2 * DOUT + (j >> 1) * 4 + 2 + (j & 1)] = Wr[i];
    }
    if (threadIdx.x < DOUT) sB[threadIdx.x] = B[threadIdx.x];
    __syncthreads();

    int lane   = threadIdx.x & 31;
    int warp   = (blockIdx.x * blockDim.x + threadIdx.x) >> 5;
    int nwarps = (gridDim.x * blockDim.x) >> 5;
    int sl     = lane & (W - 1);       // column-pair index
    int sub    = lane / W;             // node slot within warp

    for (int base = warp * NPW; base < n; base += nwarps * NPW) {
        int node = base + sub;
        bool valid = node < n;

        float xr[NX];
#pragma unroll
        for (int t = 0; t < NX; t++)
            xr[t] = valid ? X[(size_t)node * DIN + t * W + sl] : 0.0f;

        unsigned long long accL, accR;
        {
            float b0 = sB[2 * sl], b1 = sB[2 * sl + 1];
            asm("mov.b64 %0, {%1, %2};" : "=l"(accL) : "f"(0.0f), "f"(0.0f));
            asm("mov.b64 %0, {%1, %2};" : "=l"(accR) : "f"(b0), "f"(b1));
        }

#pragma unroll
        for (int t = 0; t < NX; t++) {
#pragma unroll
            for (int kk = 0; kk < W; kk++) {
                int k = t * W + kk;
                float xk = __shfl_sync(0xffffffffu, xr[t], kk, W);
                unsigned long long xd;
                asm("mov.b64 %0, {%1, %1};" : "=l"(xd) : "f"(xk));
                ulonglong2 wv = *reinterpret_cast<const ulonglong2*>(
                    &sWc[k * 2 * DOUT + 4 * sl]);
                asm("fma.rn.f32x2 %0, %1, %2, %0;" : "+l"(accL) : "l"(xd), "l"(wv.x));
                asm("fma.rn.f32x2 %0, %1, %2, %0;" : "+l"(accR) : "l"(xd), "l"(wv.y));
            }
        }

        if (valid) {
            float l0, l1, r0, r1;
            asm("mov.b64 {%0, %1}, %2;" : "=f"(l0), "=f"(l1) : "l"(accL));
            asm("mov.b64 {%0, %1}, %2;" : "=f"(r0), "=f"(r1) : "l"(accR));
            *reinterpret_cast<float2*>(&T[(size_t)node * DOUT + 2 * sl]) =
                make_float2(l0, l1);
            *reinterpret_cast<float2*>(&U[(size_t)node * DOUT + 2 * sl]) =
                make_float2(r0, r1);
        }
    }
}

// ---------------- gather + combine: h = relu(sum(t[src]) * inv + u) ---------
// One warp per destination node; coalesced row reads from L2-resident T.
template <int DOUT>
__global__ void __launch_bounds__(256)
gather_kernel(const int* __restrict__ rs, const int* __restrict__ csr,
              const float* __restrict__ T, const float* __restrict__ U,
              const float* __restrict__ inv, float* __restrict__ H, int n) {
    int node = (blockIdx.x * blockDim.x + threadIdx.x) >> 5;
    if (node >= n) return;
    int lane = threadIdx.x & 31;

    int beg = rs[node], end = rs[node + 1];

    float2 acc2 = make_float2(0.0f, 0.0f);
    float  acc1 = 0.0f;

    for (int i = beg; i < end; i += 32) {
        int m = end - i;
        if (m > 32) m = 32;
        int sidx = (lane < m) ? __ldg(csr + i + lane) : 0;
        for (int j = 0; j < m; j++) {
            int sn = __shfl_sync(0xffffffffu, sidx, j);
            if (DOUT == 64) {
                float2 v = __ldg(reinterpret_cast<const float2*>(T) +
                                 (size_t)sn * 32 + lane);
                acc2.x += v.x;
                acc2.y += v.y;
            } else if (DOUT == 32) {
                acc1 += __ldg(T + (size_t)sn * 32 + lane);
            } else {
                acc1 += __ldg(T + (size_t)sn * 16 + (lane & 15));
            }
        }
    }

    float iv = inv[node];
    if (DOUT == 64) {
        float2 u = __ldg(reinterpret_cast<const float2*>(U) + (size_t)node * 32 + lane);
        float2 h;
        h.x = fmaxf(fmaf(acc2.x, iv, u.x), 0.0f);
        h.y = fmaxf(fmaf(acc2.y, iv, u.y), 0.0f);
        reinterpret_cast<float2*>(H)[(size_t)node * 32 + lane] = h;
    } else if (DOUT == 32) {
        float u = __ldg(U + (size_t)node * 32 + lane);
        H[(size_t)node * 32 + lane] = fmaxf(fmaf(acc1, iv, u), 0.0f);
    } else {
        if (lane < 16) {
            float u = __ldg(U + (size_t)node * 16 + lane);
            H[(size_t)node * 16 + lane] = fmaxf(fmaf(acc1, iv, u), 0.0f);
        }
    }
}

// ---------------- head: out = h @ Wc + bc  (16 -> 1) ----------------
__global__ void __launch_bounds__(256)
head_kernel(const float* __restrict__ H, const float* __restrict__ Wc,
            const float* __restrict__ bc, float* __restrict__ out, int n) {
    int node = blockIdx.x * blockDim.x + threadIdx.x;
    if (node >= n) return;
    const float4* hp = reinterpret_cast<const float4*>(H + (size_t)node * 16);
    float acc = __ldg(bc);
#pragma unroll
    for (int c = 0; c < 4; c++) {
        float4 h = hp[c];
        acc = fmaf(h.x, __ldg(Wc + 4 * c + 0), acc);
        acc = fmaf(h.y, __ldg(Wc + 4 * c + 1), acc);
        acc = fmaf(h.z, __ldg(Wc + 4 * c + 2), acc);
        acc = fmaf(h.w, __ldg(Wc + 4 * c + 3), acc);
    }
    out[node] = acc;
}

// ---------------------------------------------------------------------------

extern "C" void kernel_launch(void* const* d_in, const int* in_sizes, int n_in,
                              void* d_out, int out_size) {
    const float* x   = (const float*)d_in[0];
    const int* eidx  = (const int*)d_in[1];
    const float* Wl0 = (const float*)d_in[2];
    const float* Wr0 = (const float*)d_in[3];
    const float* b0  = (const float*)d_in[4];
    const float* Wl1 = (const float*)d_in[5];
    const float* Wr1 = (const float*)d_in[6];
    const float* b1  = (const float*)d_in[7];
    const float* Wl2 = (const float*)d_in[8];
    const float* Wr2 = (const float*)d_in[9];
    const float* b2  = (const float*)d_in[10];
    const float* Wc  = (const float*)d_in[11];
    const float* bc  = (const float*)d_in[12];
    float* out = (float*)d_out;

    const int n = in_sizes[0] / 64;        // 100000
    const int e = in_sizes[1] / 2;         // 3200000
    const int* src = eidx;
    const int* dst = eidx + e;

    float *t, *u, *h, *inv;
    int *cnt, *rs, *cur, *csr, *bsum;
    cudaGetSymbolAddress((void**)&t, g_t);
    cudaGetSymbolAddress((void**)&u, g_u);
    cudaGetSymbolAddress((void**)&h, g_h);
    cudaGetSymbolAddress((void**)&inv, g_inv);
    cudaGetSymbolAddress((void**)&cnt, g_cnt);
    cudaGetSymbolAddress((void**)&rs, g_rs);
    cudaGetSymbolAddress((void**)&cur, g_cur);
    cudaGetSymbolAddress((void**)&csr, g_csr);
    cudaGetSymbolAddress((void**)&bsum, g_bsum);

    const int nb = cdiv(n, 256);           // 391 scan blocks (<=512)

    // --- CSR + inv_deg build (reused by all 3 layers) ---
    zero_cnt_kernel<<<cdiv(n, 256), 256>>>(cnt, n);
    hist_kernel<<<cdiv(e, 256), 256>>>(dst, cnt, e);
    scan1_kernel<<<nb, 256>>>(cnt, rs, bsum, n);
    scan2_kernel<<<1, 512>>>(bsum, nb);
    scan3_kernel<<<nb, 256>>>(cnt, rs, cur, inv, bsum, n);
    fill_kernel<<<cdiv(e, 256), 256>>>(src, dst, cur, csr, e);

    // --- layer 0: 64 -> 64 ---
    gemm_kernel<64, 64><<<1480, 256>>>(x, Wl0, Wr0, b0, t, u, n);
    gather_kernel<64><<<cdiv((long long)n * 32, 256), 256>>>(rs, csr, t, u, inv, h, n);

    // --- layer 1: 64 -> 32 ---
    gemm_kernel<64, 32><<<1480, 256>>>(h, Wl1, Wr1, b1, t, u, n);
    gather_kernel<32><<<cdiv((long long)n * 32, 256), 256>>>(rs, csr, t, u, inv, h, n);

    // --- layer 2: 32 -> 16 ---
    gemm_kernel<32, 16><<<1480, 256>>>(h, Wl2, Wr2, b2, t, u, n);
    gather_kernel<16><<<cdiv((long long)n * 32, 256), 256>>>(rs, csr, t, u, inv, h, n);

    // --- head: 16 -> 1 ---
    head_kernel<<<cdiv(n, 256), 256>>>(h, Wc, bc, out, n);
}

// round 3
// speedup vs baseline: 1.4966x; 1.2733x over previous
#include <cuda_runtime.h>
#include <cstdint>

// ---------------------------------------------------------------------------
// GraphSAGE: 3x SAGEConv(mean) + linear head.
// N=100000, E=3200000, dims 64 -> 64 -> 32 -> 16 -> 1
//
// v3: tiled dual GEMM (8 nodes/warp-group, f32x2, weights amortized in SMEM)
//     + CSR gather (atomic-free aggregation) fused with combine.
// ---------------------------------------------------------------------------

#define N_NODES 100000
#define MAX_E   3200000

__device__ float g_t[(size_t)N_NODES * 64];
__device__ float g_u[(size_t)N_NODES * 64];
__device__ float g_h[(size_t)N_NODES * 64];
__device__ float g_inv[N_NODES];
__device__ int   g_cnt[N_NODES];
__device__ int   g_rs[N_NODES + 1];
__device__ int   g_cur[N_NODES];
__device__ int   g_csr[MAX_E];
__device__ int   g_bsum[512];

static inline int cdiv(long long a, int b) { return (int)((a + b - 1) / b); }

// ---------------- f32x2 helpers ----------------
__device__ __forceinline__ unsigned long long dup2(float a) {
    unsigned long long r;
    asm("mov.b64 %0, {%1, %1};" : "=l"(r) : "f"(a));
    return r;
}
__device__ __forceinline__ unsigned long long pack2(float a, float b) {
    unsigned long long r;
    asm("mov.b64 %0, {%1, %2};" : "=l"(r) : "f"(a), "f"(b));
    return r;
}
__device__ __forceinline__ void unpack2(unsigned long long v, float& a, float& b) {
    asm("mov.b64 {%0, %1}, %2;" : "=f"(a), "=f"(b) : "l"(v));
}
__device__ __forceinline__ void fma2(unsigned long long& acc,
                                     unsigned long long x, unsigned long long w) {
    asm("fma.rn.f32x2 %0, %1, %2, %0;" : "+l"(acc) : "l"(x), "l"(w));
}

// ---------------- CSR build ----------------
__global__ void zero_cnt_kernel(int* __restrict__ cnt, int n) {
    int i = blockIdx.x * blockDim.x + threadIdx.x;
    if (i < n) cnt[i] = 0;
}

__global__ void hist_kernel(const int* __restrict__ dst, int* __restrict__ cnt, int e) {
    int i = blockIdx.x * blockDim.x + threadIdx.x;
    if (i < e) atomicAdd(&cnt[dst[i]], 1);
}

__global__ void __launch_bounds__(256)
scan1_kernel(const int* __restrict__ cnt, int* __restrict__ rs,
             int* __restrict__ bsum, int n) {
    __shared__ int sm[256];
    int tid = threadIdx.x;
    int gi = blockIdx.x * 256 + tid;
    int v = (gi < n) ? cnt[gi] : 0;
    sm[tid] = v;
    __syncthreads();
#pragma unroll
    for (int off = 1; off < 256; off <<= 1) {
        int t = (tid >= off) ? sm[tid - off] : 0;
        __syncthreads();
        sm[tid] += t;
        __syncthreads();
    }
    if (gi < n) rs[gi] = sm[tid] - v;
    if (tid == 255) bsum[blockIdx.x] = sm[255];
}

__global__ void __launch_bounds__(512)
scan2_kernel(int* __restrict__ bsum, int nb) {
    __shared__ int sm[512];
    int tid = threadIdx.x;
    int v = (tid < nb) ? bsum[tid] : 0;
    sm[tid] = v;
    __syncthreads();
#pragma unroll
    for (int off = 1; off < 512; off <<= 1) {
        int t = (tid >= off) ? sm[tid - off] : 0;
        __syncthreads();
        sm[tid] += t;
        __syncthreads();
    }
    if (tid < nb) bsum[tid] = sm[tid] - v;
}

__global__ void scan3_kernel(const int* __restrict__ cnt, int* __restrict__ rs,
                             int* __restrict__ cur, float* __restrict__ inv,
                             const int* __restrict__ bsum, int n) {
    int gi = blockIdx.x * blockDim.x + threadIdx.x;
    if (gi >= n) return;
    int rsv = rs[gi] + bsum[blockIdx.x];
    rs[gi] = rsv;
    cur[gi] = rsv;
    int c = cnt[gi];
    inv[gi] = 1.0f / fmaxf((float)c, 1.0f);
    if (gi == n - 1) rs[n] = rsv + c;
}

__global__ void fill_kernel(const int* __restrict__ src, const int* __restrict__ dst,
                            int* __restrict__ cur, int* __restrict__ csr, int e) {
    int i = blockIdx.x * blockDim.x + threadIdx.x;
    if (i < e) {
        int p = atomicAdd(&cur[dst[i]], 1);
        csr[p] = src[i];
    }
}

// ---------------- tiled dual GEMM: t = X@Wl, u = X@Wr + b ----------------
// Warp layout: G = 32/(DOUT/2) lane-groups; each group handles 8 nodes.
// Lane (group g, pair p) computes columns {2p, 2p+1} of both Wl and Wr for
// its group's 8 nodes. Accumulators pack two NODES per f32x2 register.
// X staged in SMEM [node][DIN+4] (natural layout, padded); weights staged
// once per block, interleaved {Wl[k][2p],Wl[k][2p+1],Wr[k][2p],Wr[k][2p+1]}.
template <int DIN, int DOUT>
__global__ void __launch_bounds__(256)
gemm_kernel(const float* __restrict__ X,
            const float* __restrict__ Wl, const float* __restrict__ Wr,
            const float* __restrict__ B,
            float* __restrict__ T, float* __restrict__ U,
            int n, int ntiles) {
    constexpr int P  = DOUT / 2;     // pairs = lanes per group (32/16/8)
    constexpr int G  = 32 / P;       // groups per warp (1/2/4)
    constexpr int WT = 8 * G;        // nodes per warp
    constexpr int BT = 8 * WT;       // nodes per block (8 warps)
    constexpr int XP = DIN + 4;      // padded x row stride (floats)

    extern __shared__ float sm[];
    float* sW = sm;                  // DIN * 2*DOUT
    float* sX = sm + DIN * 2 * DOUT; // BT * XP

    // stage interleaved weights (once per block)
    for (int i = threadIdx.x; i < DIN * DOUT; i += 256) {
        int k = i / DOUT, j = i % DOUT;
        sW[k * 2 * DOUT + 4 * (j >> 1) + (j & 1)]     = Wl[i];
        sW[k * 2 * DOUT + 4 * (j >> 1) + 2 + (j & 1)] = Wr[i];
    }

    int lane = threadIdx.x & 31;
    int warp = threadIdx.x >> 5;
    int g = lane / P;
    int p = lane % P;

    float2 bb = *reinterpret_cast<const float2*>(B + 2 * p);  // bias for cols 2p,2p+1

    for (int tile = blockIdx.x; tile < ntiles; tile += gridDim.x) {
        int nbase = tile * BT;
        __syncthreads();
        // stage X tile
        for (int i = threadIdx.x; i < BT * (DIN / 4); i += 256) {
            int node = i / (DIN / 4), kq = i % (DIN / 4);
            int gn = nbase + node;
            float4 v = make_float4(0.f, 0.f, 0.f, 0.f);
            if (gn < n) v = *reinterpret_cast<const float4*>(X + (size_t)gn * DIN + 4 * kq);
            *reinterpret_cast<float4*>(&sX[node * XP + 4 * kq]) = v;
        }
        __syncthreads();

        int ln = warp * WT + g * 8;   // local base node for this lane's group

        unsigned long long aL0[4], aL1[4], aR0[4], aR1[4];
#pragma unroll
        for (int m = 0; m < 4; m++) {
            aL0[m] = 0ull; aL1[m] = 0ull;
            aR0[m] = dup2(bb.x); aR1[m] = dup2(bb.y);
        }

#pragma unroll 8
        for (int k = 0; k < DIN; k++) {
            float4 w = *reinterpret_cast<const float4*>(&sW[k * 2 * DOUT + 4 * p]);
            unsigned long long wl0 = dup2(w.x), wl1 = dup2(w.y);
            unsigned long long wr0 = dup2(w.z), wr1 = dup2(w.w);
            float xs[8];
#pragma unroll
            for (int m = 0; m < 8; m++) xs[m] = sX[(ln + m) * XP + k];
#pragma unroll
            for (int m = 0; m < 4; m++) {
                unsigned long long xp2 = pack2(xs[2 * m], xs[2 * m + 1]);
                fma2(aL0[m], xp2, wl0);
                fma2(aL1[m], xp2, wl1);
                fma2(aR0[m], xp2, wr0);
                fma2(aR1[m], xp2, wr1);
            }
        }

        // stores: node-pair m holds nodes (2m, 2m+1) in f32x2 components
#pragma unroll
        for (int m = 0; m < 4; m++) {
            float l0a, l0b, l1a, l1b, r0a, r0b, r1a, r1b;
            unpack2(aL0[m], l0a, l0b);
            unpack2(aL1[m], l1a, l1b);
            unpack2(aR0[m], r0a, r0b);
            unpack2(aR1[m], r1a, r1b);
            int gn0 = nbase + ln + 2 * m;
            if (gn0 < n) {
                *reinterpret_cast<float2*>(&T[(size_t)gn0 * DOUT + 2 * p]) = make_float2(l0a, l1a);
                *reinterpret_cast<float2*>(&U[(size_t)gn0 * DOUT + 2 * p]) = make_float2(r0a, r1a);
            }
            if (gn0 + 1 < n) {
                *reinterpret_cast<float2*>(&T[(size_t)(gn0 + 1) * DOUT + 2 * p]) = make_float2(l0b, l1b);
                *reinterpret_cast<float2*>(&U[(size_t)(gn0 + 1) * DOUT + 2 * p]) = make_float2(r0b, r1b);
            }
        }
    }
}

// ---------------- gather + combine: h = relu(sum(t[src]) * inv + u) ---------
template <int DOUT>
__global__ void __launch_bounds__(256)
gather_kernel(const int* __restrict__ rs, const int* __restrict__ csr,
              const float* __restrict__ T, const float* __restrict__ U,
              const float* __restrict__ inv, float* __restrict__ H, int n) {
    int gid = blockIdx.x * blockDim.x + threadIdx.x;
    int lane = threadIdx.x & 31;

    if (DOUT == 16) {
        // half-warp per node
        int node = (gid >> 4);
        if (node >= n) return;
        int l = lane & 15;
        int beg = rs[node], end = rs[node + 1];
        float acc = 0.0f;
        for (int i = beg; i < end; i += 16) {
            int m = end - i;
            if (m > 16) m = 16;
            int sidx = (l < m) ? __ldg(csr + i + l) : 0;
            for (int j = 0; j < m; j++) {
                int sn = __shfl_sync(0xffffffffu, sidx, j, 16);
                acc += __ldg(T + (size_t)sn * 16 + l);
            }
        }
        float iv = inv[node];
        float u = __ldg(U + (size_t)node * 16 + l);
        H[(size_t)node * 16 + l] = fmaxf(fmaf(acc, iv, u), 0.0f);
        return;
    }

    int node = gid >> 5;
    if (node >= n) return;
    int beg = rs[node], end = rs[node + 1];

    float2 acc2 = make_float2(0.0f, 0.0f);
    float  acc1 = 0.0f;

    for (int i = beg; i < end; i += 32) {
        int m = end - i;
        if (m > 32) m = 32;
        int sidx = (lane < m) ? __ldg(csr + i + lane) : 0;
        for (int j = 0; j < m; j++) {
            int sn = __shfl_sync(0xffffffffu, sidx, j);
            if (DOUT == 64) {
                float2 v = __ldg(reinterpret_cast<const float2*>(T) + (size_t)sn * 32 + lane);
                acc2.x += v.x;
                acc2.y += v.y;
            } else {
                acc1 += __ldg(T + (size_t)sn * 32 + lane);
            }
        }
    }

    float iv = inv[node];
    if (DOUT == 64) {
        float2 u = __ldg(reinterpret_cast<const float2*>(U) + (size_t)node * 32 + lane);
        float2 h;
        h.x = fmaxf(fmaf(acc2.x, iv, u.x), 0.0f);
        h.y = fmaxf(fmaf(acc2.y, iv, u.y), 0.0f);
        reinterpret_cast<float2*>(H)[(size_t)node * 32 + lane] = h;
    } else {
        float u = __ldg(U + (size_t)node * 32 + lane);
        H[(size_t)node * 32 + lane] = fmaxf(fmaf(acc1, iv, u), 0.0f);
    }
}

// ---------------- head: out = h @ Wc + bc  (16 -> 1) ----------------
__global__ void __launch_bounds__(256)
head_kernel(const float* __restrict__ H, const float* __restrict__ Wc,
            const float* __restrict__ bc, float* __restrict__ out, int n) {
    int node = blockIdx.x * blockDim.x + threadIdx.x;
    if (node >= n) return;
    const float4* hp = reinterpret_cast<const float4*>(H + (size_t)node * 16);
    float acc = __ldg(bc);
#pragma unroll
    for (int c = 0; c < 4; c++) {
        float4 h = hp[c];
        acc = fmaf(h.x, __ldg(Wc + 4 * c + 0), acc);
        acc = fmaf(h.y, __ldg(Wc + 4 * c + 1), acc);
        acc = fmaf(h.z, __ldg(Wc + 4 * c + 2), acc);
        acc = fmaf(h.w, __ldg(Wc + 4 * c + 3), acc);
    }
    out[node] = acc;
}

// ---------------------------------------------------------------------------

template <int DIN, int DOUT>
static void launch_gemm(const float* X, const float* Wl, const float* Wr,
                        const float* B, float* T, float* U, int n) {
    constexpr int BT = 8 * 8 * (32 / (DOUT / 2));
    constexpr int SMEM = (DIN * 2 * DOUT + BT * (DIN + 4)) * (int)sizeof(float);
    int ntiles = cdiv(n, BT);
    cudaFuncSetAttribute(gemm_kernel<DIN, DOUT>,
                         cudaFuncAttributeMaxDynamicSharedMemorySize, SMEM);
    int grid = ntiles < 592 ? ntiles : 592;
    gemm_kernel<DIN, DOUT><<<grid, 256, SMEM>>>(X, Wl, Wr, B, T, U, n, ntiles);
}

extern "C" void kernel_launch(void* const* d_in, const int* in_sizes, int n_in,
                              void* d_out, int out_size) {
    const float* x   = (const float*)d_in[0];
    const int* eidx  = (const int*)d_in[1];
    const float* Wl0 = (const float*)d_in[2];
    const float* Wr0 = (const float*)d_in[3];
    const float* b0  = (const float*)d_in[4];
    const float* Wl1 = (const float*)d_in[5];
    const float* Wr1 = (const float*)d_in[6];
    const float* b1  = (const float*)d_in[7];
    const float* Wl2 = (const float*)d_in[8];
    const float* Wr2 = (const float*)d_in[9];
    const float* b2  = (const float*)d_in[10];
    const float* Wc  = (const float*)d_in[11];
    const float* bc  = (const float*)d_in[12];
    float* out = (float*)d_out;

    const int n = in_sizes[0] / 64;        // 100000
    const int e = in_sizes[1] / 2;         // 3200000
    const int* src = eidx;
    const int* dst = eidx + e;

    float *t, *u, *h, *inv;
    int *cnt, *rs, *cur, *csr, *bsum;
    cudaGetSymbolAddress((void**)&t, g_t);
    cudaGetSymbolAddress((void**)&u, g_u);
    cudaGetSymbolAddress((void**)&h, g_h);
    cudaGetSymbolAddress((void**)&inv, g_inv);
    cudaGetSymbolAddress((void**)&cnt, g_cnt);
    cudaGetSymbolAddress((void**)&rs, g_rs);
    cudaGetSymbolAddress((void**)&cur, g_cur);
    cudaGetSymbolAddress((void**)&csr, g_csr);
    cudaGetSymbolAddress((void**)&bsum, g_bsum);

    const int nb = cdiv(n, 256);

    // --- CSR + inv_deg (built once, reused 3x) ---
    zero_cnt_kernel<<<cdiv(n, 256), 256>>>(cnt, n);
    hist_kernel<<<cdiv(e, 256), 256>>>(dst, cnt, e);
    scan1_kernel<<<nb, 256>>>(cnt, rs, bsum, n);
    scan2_kernel<<<1, 512>>>(bsum, nb);
    scan3_kernel<<<nb, 256>>>(cnt, rs, cur, inv, bsum, n);
    fill_kernel<<<cdiv(e, 256), 256>>>(src, dst, cur, csr, e);

    // --- layer 0: 64 -> 64 ---
    launch_gemm<64, 64>(x, Wl0, Wr0, b0, t, u, n);
    gather_kernel<64><<<cdiv((long long)n * 32, 256), 256>>>(rs, csr, t, u, inv, h, n);

    // --- layer 1: 64 -> 32 ---
    launch_gemm<64, 32>(h, Wl1, Wr1, b1, t, u, n);
    gather_kernel<32><<<cdiv((long long)n * 32, 256), 256>>>(rs, csr, t, u, inv, h, n);

    // --- layer 2: 32 -> 16 ---
    launch_gemm<32, 16>(h, Wl2, Wr2, b2, t, u, n);
    gather_kernel<16><<<cdiv((long long)n * 16, 256), 256>>>(rs, csr, t, u, inv, h, n);

    // --- head: 16 -> 1 ---
    head_kernel<<<cdiv(n, 256), 256>>>(h, Wc, bc, out, n);
}

// round 4
// speedup vs baseline: 1.6360x; 1.0931x over previous
#include <cuda_runtime.h>
#include <cstdint>

// ---------------------------------------------------------------------------
// GraphSAGE: 3x SAGEConv(mean) + linear head.
// N=100000, E=3200000, dims 64 -> 64 -> 32 -> 16 -> 1
//
// v4: gather restructured for MLP=4 (uniform index loads, explicit unroll,
//     dual accumulator chains); head fused into layer-2 gather.
//     Tiled dual GEMM (f32x2) + once-per-launch CSR unchanged from v3.
// ---------------------------------------------------------------------------

#define N_NODES 100000
#define MAX_E   3200000

__device__ float g_t[(size_t)N_NODES * 64];
__device__ float g_u[(size_t)N_NODES * 64];
__device__ float g_h[(size_t)N_NODES * 64];
__device__ float g_inv[N_NODES];
__device__ int   g_cnt[N_NODES];
__device__ int   g_rs[N_NODES + 1];
__device__ int   g_cur[N_NODES];
__device__ int   g_csr[MAX_E];
__device__ int   g_bsum[512];

static inline int cdiv(long long a, int b) { return (int)((a + b - 1) / b); }

// ---------------- f32x2 helpers ----------------
__device__ __forceinline__ unsigned long long dup2(float a) {
    unsigned long long r;
    asm("mov.b64 %0, {%1, %1};" : "=l"(r) : "f"(a));
    return r;
}
__device__ __forceinline__ unsigned long long pack2(float a, float b) {
    unsigned long long r;
    asm("mov.b64 %0, {%1, %2};" : "=l"(r) : "f"(a), "f"(b));
    return r;
}
__device__ __forceinline__ void unpack2(unsigned long long v, float& a, float& b) {
    asm("mov.b64 {%0, %1}, %2;" : "=f"(a), "=f"(b) : "l"(v));
}
__device__ __forceinline__ void fma2(unsigned long long& acc,
                                     unsigned long long x, unsigned long long w) {
    asm("fma.rn.f32x2 %0, %1, %2, %0;" : "+l"(acc) : "l"(x), "l"(w));
}

// ---------------- CSR build ----------------
__global__ void zero_cnt_kernel(int* __restrict__ cnt, int n) {
    int i = blockIdx.x * blockDim.x + threadIdx.x;
    if (i < n) cnt[i] = 0;
}

__global__ void hist_kernel(const int* __restrict__ dst, int* __restrict__ cnt, int e) {
    int i = blockIdx.x * blockDim.x + threadIdx.x;
    if (i < e) atomicAdd(&cnt[dst[i]], 1);
}

__global__ void __launch_bounds__(256)
scan1_kernel(const int* __restrict__ cnt, int* __restrict__ rs,
             int* __restrict__ bsum, int n) {
    __shared__ int sm[256];
    int tid = threadIdx.x;
    int gi = blockIdx.x * 256 + tid;
    int v = (gi < n) ? cnt[gi] : 0;
    sm[tid] = v;
    __syncthreads();
#pragma unroll
    for (int off = 1; off < 256; off <<= 1) {
        int t = (tid >= off) ? sm[tid - off] : 0;
        __syncthreads();
        sm[tid] += t;
        __syncthreads();
    }
    if (gi < n) rs[gi] = sm[tid] - v;
    if (tid == 255) bsum[blockIdx.x] = sm[255];
}

__global__ void __launch_bounds__(512)
scan2_kernel(int* __restrict__ bsum, int nb) {
    __shared__ int sm[512];
    int tid = threadIdx.x;
    int v = (tid < nb) ? bsum[tid] : 0;
    sm[tid] = v;
    __syncthreads();
#pragma unroll
    for (int off = 1; off < 512; off <<= 1) {
        int t = (tid >= off) ? sm[tid - off] : 0;
        __syncthreads();
        sm[tid] += t;
        __syncthreads();
    }
    if (tid < nb) bsum[tid] = sm[tid] - v;
}

__global__ void scan3_kernel(const int* __restrict__ cnt, int* __restrict__ rs,
                             int* __restrict__ cur, float* __restrict__ inv,
                             const int* __restrict__ bsum, int n) {
    int gi = blockIdx.x * blockDim.x + threadIdx.x;
    if (gi >= n) return;
    int rsv = rs[gi] + bsum[blockIdx.x];
    rs[gi] = rsv;
    cur[gi] = rsv;
    int c = cnt[gi];
    inv[gi] = 1.0f / fmaxf((float)c, 1.0f);
    if (gi == n - 1) rs[n] = rsv + c;
}

__global__ void fill_kernel(const int* __restrict__ src, const int* __restrict__ dst,
                            int* __restrict__ cur, int* __restrict__ csr, int e) {
    int i = blockIdx.x * blockDim.x + threadIdx.x;
    if (i < e) {
        int p = atomicAdd(&cur[dst[i]], 1);
        csr[p] = src[i];
    }
}

// ---------------- tiled dual GEMM: t = X@Wl, u = X@Wr + b ----------------
template <int DIN, int DOUT>
__global__ void __launch_bounds__(256)
gemm_kernel(const float* __restrict__ X,
            const float* __restrict__ Wl, const float* __restrict__ Wr,
            const float* __restrict__ B,
            float* __restrict__ T, float* __restrict__ U,
            int n, int ntiles) {
    constexpr int P  = DOUT / 2;
    constexpr int G  = 32 / P;
    constexpr int WT = 8 * G;
    constexpr int BT = 8 * WT;
    constexpr int XP = DIN + 4;

    extern __shared__ float sm[];
    float* sW = sm;
    float* sX = sm + DIN * 2 * DOUT;

    for (int i = threadIdx.x; i < DIN * DOUT; i += 256) {
        int k = i / DOUT, j = i % DOUT;
        sW[k * 2 * DOUT + 4 * (j >> 1) + (j & 1)]     = Wl[i];
        sW[k * 2 * DOUT + 4 * (j >> 1) + 2 + (j & 1)] = Wr[i];
    }

    int lane = threadIdx.x & 31;
    int warp = threadIdx.x >> 5;
    int g = lane / P;
    int p = lane % P;

    float2 bb = *reinterpret_cast<const float2*>(B + 2 * p);

    for (int tile = blockIdx.x; tile < ntiles; tile += gridDim.x) {
        int nbase = tile * BT;
        __syncthreads();
        for (int i = threadIdx.x; i < BT * (DIN / 4); i += 256) {
            int node = i / (DIN / 4), kq = i % (DIN / 4);
            int gn = nbase + node;
            float4 v = make_float4(0.f, 0.f, 0.f, 0.f);
            if (gn < n) v = *reinterpret_cast<const float4*>(X + (size_t)gn * DIN + 4 * kq);
            *reinterpret_cast<float4*>(&sX[node * XP + 4 * kq]) = v;
        }
        __syncthreads();

        int ln = warp * WT + g * 8;

        unsigned long long aL0[4], aL1[4], aR0[4], aR1[4];
#pragma unroll
        for (int m = 0; m < 4; m++) {
            aL0[m] = 0ull; aL1[m] = 0ull;
            aR0[m] = dup2(bb.x); aR1[m] = dup2(bb.y);
        }

#pragma unroll 8
        for (int k = 0; k < DIN; k++) {
            float4 w = *reinterpret_cast<const float4*>(&sW[k * 2 * DOUT + 4 * p]);
            unsigned long long wl0 = dup2(w.x), wl1 = dup2(w.y);
            unsigned long long wr0 = dup2(w.z), wr1 = dup2(w.w);
            float xs[8];
#pragma unroll
            for (int m = 0; m < 8; m++) xs[m] = sX[(ln + m) * XP + k];
#pragma unroll
            for (int m = 0; m < 4; m++) {
                unsigned long long xp2 = pack2(xs[2 * m], xs[2 * m + 1]);
                fma2(aL0[m], xp2, wl0);
                fma2(aL1[m], xp2, wl1);
                fma2(aR0[m], xp2, wr0);
                fma2(aR1[m], xp2, wr1);
            }
        }

#pragma unroll
        for (int m = 0; m < 4; m++) {
            float l0a, l0b, l1a, l1b, r0a, r0b, r1a, r1b;
            unpack2(aL0[m], l0a, l0b);
            unpack2(aL1[m], l1a, l1b);
            unpack2(aR0[m], r0a, r0b);
            unpack2(aR1[m], r1a, r1b);
            int gn0 = nbase + ln + 2 * m;
            if (gn0 < n) {
                *reinterpret_cast<float2*>(&T[(size_t)gn0 * DOUT + 2 * p]) = make_float2(l0a, l1a);
                *reinterpret_cast<float2*>(&U[(size_t)gn0 * DOUT + 2 * p]) = make_float2(r0a, r1a);
            }
            if (gn0 + 1 < n) {
                *reinterpret_cast<float2*>(&T[(size_t)(gn0 + 1) * DOUT + 2 * p]) = make_float2(l0b, l1b);
                *reinterpret_cast<float2*>(&U[(size_t)(gn0 + 1) * DOUT + 2 * p]) = make_float2(r0b, r1b);
            }
        }
    }
}

// ---------------- gather + combine, MLP-4 unrolled ----------------
// Index loads are warp-uniform (__ldg same address -> broadcast), so no shfl
// in the dependence chain; 4 independent row loads in flight per warp.

__global__ void __launch_bounds__(256)
gather64_kernel(const int* __restrict__ rs, const int* __restrict__ csr,
                const float* __restrict__ T, const float* __restrict__ U,
                const float* __restrict__ inv, float* __restrict__ H, int n) {
    int node = (blockIdx.x * blockDim.x + threadIdx.x) >> 5;
    if (node >= n) return;
    int lane = threadIdx.x & 31;

    int beg = rs[node], end = rs[node + 1];
    float iv = inv[node];

    float2 aA = make_float2(0.f, 0.f), aB = make_float2(0.f, 0.f);
    const float2* T2 = reinterpret_cast<const float2*>(T);

    int i = beg;
    for (; i + 4 <= end; i += 4) {
        int s0 = __ldg(csr + i + 0);
        int s1 = __ldg(csr + i + 1);
        int s2 = __ldg(csr + i + 2);
        int s3 = __ldg(csr + i + 3);
        float2 v0 = __ldg(T2 + (size_t)s0 * 32 + lane);
        float2 v1 = __ldg(T2 + (size_t)s1 * 32 + lane);
        float2 v2 = __ldg(T2 + (size_t)s2 * 32 + lane);
        float2 v3 = __ldg(T2 + (size_t)s3 * 32 + lane);
        aA.x += v0.x + v1.x; aA.y += v0.y + v1.y;
        aB.x += v2.x + v3.x; aB.y += v2.y + v3.y;
    }
    for (; i < end; i++) {
        int s0 = __ldg(csr + i);
        float2 v0 = __ldg(T2 + (size_t)s0 * 32 + lane);
        aA.x += v0.x; aA.y += v0.y;
    }

    float2 u = __ldg(reinterpret_cast<const float2*>(U) + (size_t)node * 32 + lane);
    float2 h;
    h.x = fmaxf(fmaf(aA.x + aB.x, iv, u.x), 0.0f);
    h.y = fmaxf(fmaf(aA.y + aB.y, iv, u.y), 0.0f);
    reinterpret_cast<float2*>(H)[(size_t)node * 32 + lane] = h;
}

__global__ void __launch_bounds__(256)
gather32_kernel(const int* __restrict__ rs, const int* __restrict__ csr,
                const float* __restrict__ T, const float* __restrict__ U,
                const float* __restrict__ inv, float* __restrict__ H, int n) {
    int node = (blockIdx.x * blockDim.x + threadIdx.x) >> 5;
    if (node >= n) return;
    int lane = threadIdx.x & 31;

    int beg = rs[node], end = rs[node + 1];
    float iv = inv[node];

    float aA = 0.f, aB = 0.f;

    int i = beg;
    for (; i + 4 <= end; i += 4) {
        int s0 = __ldg(csr + i + 0);
        int s1 = __ldg(csr + i + 1);
        int s2 = __ldg(csr + i + 2);
        int s3 = __ldg(csr + i + 3);
        float v0 = __ldg(T + (size_t)s0 * 32 + lane);
        float v1 = __ldg(T + (size_t)s1 * 32 + lane);
        float v2 = __ldg(T + (size_t)s2 * 32 + lane);
        float v3 = __ldg(T + (size_t)s3 * 32 + lane);
        aA += v0 + v1;
        aB += v2 + v3;
    }
    for (; i < end; i++) {
        int s0 = __ldg(csr + i);
        aA += __ldg(T + (size_t)s0 * 32 + lane);
    }

    float u = __ldg(U + (size_t)node * 32 + lane);
    H[(size_t)node * 32 + lane] = fmaxf(fmaf(aA + aB, iv, u), 0.0f);
}

// layer-2 gather (DOUT=16) fused with the 16->1 head:
// half-warp per node; after combine, reduce h*Wc across the 16 lanes.
__global__ void __launch_bounds__(256)
gather16_head_kernel(const int* __restrict__ rs, const int* __restrict__ csr,
                     const float* __restrict__ T, const float* __restrict__ U,
                     const float* __restrict__ inv,
                     const float* __restrict__ Wc, const float* __restrict__ bc,
                     float* __restrict__ out, int n) {
    int node = (blockIdx.x * blockDim.x + threadIdx.x) >> 4;
    if (node >= n) return;
    int l = threadIdx.x & 15;

    int beg = rs[node], end = rs[node + 1];
    float iv = inv[node];

    float aA = 0.f, aB = 0.f;

    int i = beg;
    for (; i + 4 <= end; i += 4) {
        int s0 = __ldg(csr + i + 0);
        int s1 = __ldg(csr + i + 1);
        int s2 = __ldg(csr + i + 2);
        int s3 = __ldg(csr + i + 3);
        float v0 = __ldg(T + (size_t)s0 * 16 + l);
        float v1 = __ldg(T + (size_t)s1 * 16 + l);
        float v2 = __ldg(T + (size_t)s2 * 16 + l);
        float v3 = __ldg(T + (size_t)s3 * 16 + l);
        aA += v0 + v1;
        aB += v2 + v3;
    }
    for (; i < end; i++) {
        int s0 = __ldg(csr + i);
        aA += __ldg(T + (size_t)s0 * 16 + l);
    }

    float u = __ldg(U + (size_t)node * 16 + l);
    float h = fmaxf(fmaf(aA + aB, iv, u), 0.0f);

    float prod = h * __ldg(Wc + l);
#pragma unroll
    for (int off = 8; off > 0; off >>= 1)
        prod += __shfl_down_sync(0xffffffffu, prod, off, 16);
    if (l == 0) out[node] = prod + __ldg(bc);
}

// ---------------------------------------------------------------------------

template <int DIN, int DOUT>
static void launch_gemm(const float* X, const float* Wl, const float* Wr,
                        const float* B, float* T, float* U, int n) {
    constexpr int BT = 8 * 8 * (32 / (DOUT / 2));
    constexpr int SMEM = (DIN * 2 * DOUT + BT * (DIN + 4)) * (int)sizeof(float);
    int ntiles = cdiv(n, BT);
    cudaFuncSetAttribute(gemm_kernel<DIN, DOUT>,
                         cudaFuncAttributeMaxDynamicSharedMemorySize, SMEM);
    int grid = ntiles < 592 ? ntiles : 592;
    gemm_kernel<DIN, DOUT><<<grid, 256, SMEM>>>(X, Wl, Wr, B, T, U, n, ntiles);
}

extern "C" void kernel_launch(void* const* d_in, const int* in_sizes, int n_in,
                              void* d_out, int out_size) {
    const float* x   = (const float*)d_in[0];
    const int* eidx  = (const int*)d_in[1];
    const float* Wl0 = (const float*)d_in[2];
    const float* Wr0 = (const float*)d_in[3];
    const float* b0  = (const float*)d_in[4];
    const float* Wl1 = (const float*)d_in[5];
    const float* Wr1 = (const float*)d_in[6];
    const float* b1  = (const float*)d_in[7];
    const float* Wl2 = (const float*)d_in[8];
    const float* Wr2 = (const float*)d_in[9];
    const float* b2  = (const float*)d_in[10];
    const float* Wc  = (const float*)d_in[11];
    const float* bc  = (const float*)d_in[12];
    float* out = (float*)d_out;

    const int n = in_sizes[0] / 64;        // 100000
    const int e = in_sizes[1] / 2;         // 3200000
    const int* src = eidx;
    const int* dst = eidx + e;

    float *t, *u, *h, *inv;
    int *cnt, *rs, *cur, *csr, *bsum;
    cudaGetSymbolAddress((void**)&t, g_t);
    cudaGetSymbolAddress((void**)&u, g_u);
    cudaGetSymbolAddress((void**)&h, g_h);
    cudaGetSymbolAddress((void**)&inv, g_inv);
    cudaGetSymbolAddress((void**)&cnt, g_cnt);
    cudaGetSymbolAddress((void**)&rs, g_rs);
    cudaGetSymbolAddress((void**)&cur, g_cur);
    cudaGetSymbolAddress((void**)&csr, g_csr);
    cudaGetSymbolAddress((void**)&bsum, g_bsum);

    const int nb = cdiv(n, 256);

    // --- CSR + inv_deg (built once, reused 3x) ---
    zero_cnt_kernel<<<cdiv(n, 256), 256>>>(cnt, n);
    hist_kernel<<<cdiv(e, 256), 256>>>(dst, cnt, e);
    scan1_kernel<<<nb, 256>>>(cnt, rs, bsum, n);
    scan2_kernel<<<1, 512>>>(bsum, nb);
    scan3_kernel<<<nb, 256>>>(cnt, rs, cur, inv, bsum, n);
    fill_kernel<<<cdiv(e, 256), 256>>>(src, dst, cur, csr, e);

    // --- layer 0: 64 -> 64 ---
    launch_gemm<64, 64>(x, Wl0, Wr0, b0, t, u, n);
    gather64_kernel<<<cdiv((long long)n * 32, 256), 256>>>(rs, csr, t, u, inv, h, n);

    // --- layer 1: 64 -> 32 ---
    launch_gemm<64, 32>(h, Wl1, Wr1, b1, t, u, n);
    gather32_kernel<<<cdiv((long long)n * 32, 256), 256>>>(rs, csr, t, u, inv, h, n);

    // --- layer 2: 32 -> 16, fused with 16 -> 1 head ---
    launch_gemm<32, 16>(h, Wl2, Wr2, b2, t, u, n);
    gather16_head_kernel<<<cdiv((long long)n * 16, 256), 256>>>(rs, csr, t, u, inv,
                                                                Wc, bc, out, n);
}

// round 5
// speedup vs baseline: 1.7326x; 1.0591x over previous
#include <cuda_runtime.h>
#include <cstdint>

// ---------------------------------------------------------------------------
// GraphSAGE: 3x SAGEConv(mean) + linear head.
// N=100000, E=3200000, dims 64 -> 64 -> 32 -> 16 -> 1
//
// v5: gathers vectorized to float4 row reads with lane sub-groups
//     (2/4/8 edges per LDG.128 instruction) -> LDG count cut 2-4x;
//     dual load chains for MLP; head fused into layer-2 gather.
//     Tiled dual GEMM (f32x2) + once-per-launch CSR unchanged.
// ---------------------------------------------------------------------------

#define N_NODES 100000
#define MAX_E   3200000

__device__ float g_t[(size_t)N_NODES * 64];
__device__ float g_u[(size_t)N_NODES * 64];
__device__ float g_h[(size_t)N_NODES * 64];
__device__ float g_inv[N_NODES];
__device__ int   g_cnt[N_NODES];
__device__ int   g_rs[N_NODES + 1];
__device__ int   g_cur[N_NODES];
__device__ int   g_csr[MAX_E];
__device__ int   g_bsum[512];

static inline int cdiv(long long a, int b) { return (int)((a + b - 1) / b); }

// ---------------- f32x2 helpers ----------------
__device__ __forceinline__ unsigned long long dup2(float a) {
    unsigned long long r;
    asm("mov.b64 %0, {%1, %1};" : "=l"(r) : "f"(a));
    return r;
}
__device__ __forceinline__ unsigned long long pack2(float a, float b) {
    unsigned long long r;
    asm("mov.b64 %0, {%1, %2};" : "=l"(r) : "f"(a), "f"(b));
    return r;
}
__device__ __forceinline__ void unpack2(unsigned long long v, float& a, float& b) {
    asm("mov.b64 {%0, %1}, %2;" : "=f"(a), "=f"(b) : "l"(v));
}
__device__ __forceinline__ void fma2(unsigned long long& acc,
                                     unsigned long long x, unsigned long long w) {
    asm("fma.rn.f32x2 %0, %1, %2, %0;" : "+l"(acc) : "l"(x), "l"(w));
}

__device__ __forceinline__ void acc4(float4& a, const float4& v) {
    a.x += v.x; a.y += v.y; a.z += v.z; a.w += v.w;
}

// ---------------- CSR build ----------------
__global__ void zero_cnt_kernel(int* __restrict__ cnt, int n) {
    int i = blockIdx.x * blockDim.x + threadIdx.x;
    if (i < n) cnt[i] = 0;
}

__global__ void hist_kernel(const int* __restrict__ dst, int* __restrict__ cnt, int e) {
    int i = blockIdx.x * blockDim.x + threadIdx.x;
    if (i < e) atomicAdd(&cnt[dst[i]], 1);
}

__global__ void __launch_bounds__(256)
scan1_kernel(const int* __restrict__ cnt, int* __restrict__ rs,
             int* __restrict__ bsum, int n) {
    __shared__ int sm[256];
    int tid = threadIdx.x;
    int gi = blockIdx.x * 256 + tid;
    int v = (gi < n) ? cnt[gi] : 0;
    sm[tid] = v;
    __syncthreads();
#pragma unroll
    for (int off = 1; off < 256; off <<= 1) {
        int t = (tid >= off) ? sm[tid - off] : 0;
        __syncthreads();
        sm[tid] += t;
        __syncthreads();
    }
    if (gi < n) rs[gi] = sm[tid] - v;
    if (tid == 255) bsum[blockIdx.x] = sm[255];
}

__global__ void __launch_bounds__(512)
scan2_kernel(int* __restrict__ bsum, int nb) {
    __shared__ int sm[512];
    int tid = threadIdx.x;
    int v = (tid < nb) ? bsum[tid] : 0;
    sm[tid] = v;
    __syncthreads();
#pragma unroll
    for (int off = 1; off < 512; off <<= 1) {
        int t = (tid >= off) ? sm[tid - off] : 0;
        __syncthreads();
        sm[tid] += t;
        __syncthreads();
    }
    if (tid < nb) bsum[tid] = sm[tid] - v;
}

__global__ void scan3_kernel(const int* __restrict__ cnt, int* __restrict__ rs,
                             int* __restrict__ cur, float* __restrict__ inv,
                             const int* __restrict__ bsum, int n) {
    int gi = blockIdx.x * blockDim.x + threadIdx.x;
    if (gi >= n) return;
    int rsv = rs[gi] + bsum[blockIdx.x];
    rs[gi] = rsv;
    cur[gi] = rsv;
    int c = cnt[gi];
    inv[gi] = 1.0f / fmaxf((float)c, 1.0f);
    if (gi == n - 1) rs[n] = rsv + c;
}

__global__ void fill_kernel(const int* __restrict__ src, const int* __restrict__ dst,
                            int* __restrict__ cur, int* __restrict__ csr, int e) {
    int i = blockIdx.x * blockDim.x + threadIdx.x;
    if (i < e) {
        int p = atomicAdd(&cur[dst[i]], 1);
        csr[p] = src[i];
    }
}

// ---------------- tiled dual GEMM: t = X@Wl, u = X@Wr + b ----------------
template <int DIN, int DOUT>
__global__ void __launch_bounds__(256)
gemm_kernel(const float* __restrict__ X,
            const float* __restrict__ Wl, const float* __restrict__ Wr,
            const float* __restrict__ B,
            float* __restrict__ T, float* __restrict__ U,
            int n, int ntiles) {
    constexpr int P  = DOUT / 2;
    constexpr int G  = 32 / P;
    constexpr int WT = 8 * G;
    constexpr int BT = 8 * WT;
    constexpr int XP = DIN + 4;

    extern __shared__ float sm[];
    float* sW = sm;
    float* sX = sm + DIN * 2 * DOUT;

    for (int i = threadIdx.x; i < DIN * DOUT; i += 256) {
        int k = i / DOUT, j = i % DOUT;
        sW[k * 2 * DOUT + 4 * (j >> 1) + (j & 1)]     = Wl[i];
        sW[k * 2 * DOUT + 4 * (j >> 1) + 2 + (j & 1)] = Wr[i];
    }

    int lane = threadIdx.x & 31;
    int warp = threadIdx.x >> 5;
    int g = lane / P;
    int p = lane % P;

    float2 bb = *reinterpret_cast<const float2*>(B + 2 * p);

    for (int tile = blockIdx.x; tile < ntiles; tile += gridDim.x) {
        int nbase = tile * BT;
        __syncthreads();
        for (int i = threadIdx.x; i < BT * (DIN / 4); i += 256) {
            int node = i / (DIN / 4), kq = i % (DIN / 4);
            int gn = nbase + node;
            float4 v = make_float4(0.f, 0.f, 0.f, 0.f);
            if (gn < n) v = *reinterpret_cast<const float4*>(X + (size_t)gn * DIN + 4 * kq);
            *reinterpret_cast<float4*>(&sX[node * XP + 4 * kq]) = v;
        }
        __syncthreads();

        int ln = warp * WT + g * 8;

        unsigned long long aL0[4], aL1[4], aR0[4], aR1[4];
#pragma unroll
        for (int m = 0; m < 4; m++) {
            aL0[m] = 0ull; aL1[m] = 0ull;
            aR0[m] = dup2(bb.x); aR1[m] = dup2(bb.y);
        }

#pragma unroll 8
        for (int k = 0; k < DIN; k++) {
            float4 w = *reinterpret_cast<const float4*>(&sW[k * 2 * DOUT + 4 * p]);
            unsigned long long wl0 = dup2(w.x), wl1 = dup2(w.y);
            unsigned long long wr0 = dup2(w.z), wr1 = dup2(w.w);
            float xs[8];
#pragma unroll
            for (int m = 0; m < 8; m++) xs[m] = sX[(ln + m) * XP + k];
#pragma unroll
            for (int m = 0; m < 4; m++) {
                unsigned long long xp2 = pack2(xs[2 * m], xs[2 * m + 1]);
                fma2(aL0[m], xp2, wl0);
                fma2(aL1[m], xp2, wl1);
                fma2(aR0[m], xp2, wr0);
                fma2(aR1[m], xp2, wr1);
            }
        }

#pragma unroll
        for (int m = 0; m < 4; m++) {
            float l0a, l0b, l1a, l1b, r0a, r0b, r1a, r1b;
            unpack2(aL0[m], l0a, l0b);
            unpack2(aL1[m], l1a, l1b);
            unpack2(aR0[m], r0a, r0b);
            unpack2(aR1[m], r1a, r1b);
            int gn0 = nbase + ln + 2 * m;
            if (gn0 < n) {
                *reinterpret_cast<float2*>(&T[(size_t)gn0 * DOUT + 2 * p]) = make_float2(l0a, l1a);
                *reinterpret_cast<float2*>(&U[(size_t)gn0 * DOUT + 2 * p]) = make_float2(r0a, r1a);
            }
            if (gn0 + 1 < n) {
                *reinterpret_cast<float2*>(&T[(size_t)(gn0 + 1) * DOUT + 2 * p]) = make_float2(l0b, l1b);
                *reinterpret_cast<float2*>(&U[(size_t)(gn0 + 1) * DOUT + 2 * p]) = make_float2(r0b, r1b);
            }
        }
    }
}

// ---------------- gathers: float4 rows, multi-edge per instruction ----------

// DOUT=64: half-warp (16 lanes x float4 = 256B) per edge row; 2 edges/instr.
__global__ void __launch_bounds__(256)
gather64_kernel(const int* __restrict__ rs, const int* __restrict__ csr,
                const float* __restrict__ T, const float* __restrict__ U,
                const float* __restrict__ inv, float* __restrict__ H, int n) {
    int node = (blockIdx.x * blockDim.x + threadIdx.x) >> 5;
    if (node >= n) return;
    int lane = threadIdx.x & 31;
    int half = lane >> 4, l16 = lane & 15;

    int beg = rs[node], end = rs[node + 1];
    float iv = inv[node];
    const float4* T4 = reinterpret_cast<const float4*>(T);

    float4 aA = make_float4(0.f, 0.f, 0.f, 0.f);
    float4 aB = make_float4(0.f, 0.f, 0.f, 0.f);

    int i = beg;
    for (; i + 4 <= end; i += 4) {
        int s0 = __ldg(csr + i + half);          // edges i, i+1
        int s1 = __ldg(csr + i + 2 + half);      // edges i+2, i+3
        float4 v0 = __ldg(T4 + (size_t)s0 * 16 + l16);
        float4 v1 = __ldg(T4 + (size_t)s1 * 16 + l16);
        acc4(aA, v0);
        acc4(aB, v1);
    }
    for (; i < end; i += 2) {
        int e = i + half;
        if (e < end) {
            int s = __ldg(csr + e);
            float4 v = __ldg(T4 + (size_t)s * 16 + l16);
            acc4(aA, v);
        }
    }
    acc4(aA, aB);
    aA.x += __shfl_down_sync(0xffffffffu, aA.x, 16);
    aA.y += __shfl_down_sync(0xffffffffu, aA.y, 16);
    aA.z += __shfl_down_sync(0xffffffffu, aA.z, 16);
    aA.w += __shfl_down_sync(0xffffffffu, aA.w, 16);

    if (half == 0) {
        float4 u = __ldg(reinterpret_cast<const float4*>(U) + (size_t)node * 16 + l16);
        float4 h;
        h.x = fmaxf(fmaf(aA.x, iv, u.x), 0.0f);
        h.y = fmaxf(fmaf(aA.y, iv, u.y), 0.0f);
        h.z = fmaxf(fmaf(aA.z, iv, u.z), 0.0f);
        h.w = fmaxf(fmaf(aA.w, iv, u.w), 0.0f);
        reinterpret_cast<float4*>(H)[(size_t)node * 16 + l16] = h;
    }
}

// DOUT=32: quarter-warp (8 lanes x float4 = 128B) per edge row; 4 edges/instr.
__global__ void __launch_bounds__(256)
gather32_kernel(const int* __restrict__ rs, const int* __restrict__ csr,
                const float* __restrict__ T, const float* __restrict__ U,
                const float* __restrict__ inv, float* __restrict__ H, int n) {
    int node = (blockIdx.x * blockDim.x + threadIdx.x) >> 5;
    if (node >= n) return;
    int lane = threadIdx.x & 31;
    int q = lane >> 3, l8 = lane & 7;

    int beg = rs[node], end = rs[node + 1];
    float iv = inv[node];
    const float4* T4 = reinterpret_cast<const float4*>(T);

    float4 aA = make_float4(0.f, 0.f, 0.f, 0.f);
    float4 aB = make_float4(0.f, 0.f, 0.f, 0.f);

    int i = beg;
    for (; i + 8 <= end; i += 8) {
        int s0 = __ldg(csr + i + q);             // edges i .. i+3
        int s1 = __ldg(csr + i + 4 + q);         // edges i+4 .. i+7
        float4 v0 = __ldg(T4 + (size_t)s0 * 8 + l8);
        float4 v1 = __ldg(T4 + (size_t)s1 * 8 + l8);
        acc4(aA, v0);
        acc4(aB, v1);
    }
    for (; i < end; i += 4) {
        int e = i + q;
        if (e < end) {
            int s = __ldg(csr + e);
            float4 v = __ldg(T4 + (size_t)s * 8 + l8);
            acc4(aA, v);
        }
    }
    acc4(aA, aB);
#pragma unroll
    for (int off = 8; off <= 16; off <<= 1) {
        aA.x += __shfl_down_sync(0xffffffffu, aA.x, off);
        aA.y += __shfl_down_sync(0xffffffffu, aA.y, off);
        aA.z += __shfl_down_sync(0xffffffffu, aA.z, off);
        aA.w += __shfl_down_sync(0xffffffffu, aA.w, off);
    }

    if (lane < 8) {
        float4 u = __ldg(reinterpret_cast<const float4*>(U) + (size_t)node * 8 + l8);
        float4 h;
        h.x = fmaxf(fmaf(aA.x, iv, u.x), 0.0f);
        h.y = fmaxf(fmaf(aA.y, iv, u.y), 0.0f);
        h.z = fmaxf(fmaf(aA.z, iv, u.z), 0.0f);
        h.w = fmaxf(fmaf(aA.w, iv, u.w), 0.0f);
        reinterpret_cast<float4*>(H)[(size_t)node * 8 + l8] = h;
    }
}

// DOUT=16 + fused 16->1 head: 4-lane groups (4 x float4 = 64B); 8 edges/instr.
__global__ void __launch_bounds__(256)
gather16_head_kernel(const int* __restrict__ rs, const int* __restrict__ csr,
                     const float* __restrict__ T, const float* __restrict__ U,
                     const float* __restrict__ inv,
                     const float* __restrict__ Wc, const float* __restrict__ bc,
                     float* __restrict__ out, int n) {
    int node = (blockIdx.x * blockDim.x + threadIdx.x) >> 5;
    if (node >= n) return;
    int lane = threadIdx.x & 31;
    int g = lane >> 2, l4 = lane & 3;

    int beg = rs[node], end = rs[node + 1];
    float iv = inv[node];
    const float4* T4 = reinterpret_cast<const float4*>(T);

    float4 aA = make_float4(0.f, 0.f, 0.f, 0.f);
    float4 aB = make_float4(0.f, 0.f, 0.f, 0.f);

    int i = beg;
    for (; i + 16 <= end; i += 16) {
        int s0 = __ldg(csr + i + g);             // edges i .. i+7
        int s1 = __ldg(csr + i + 8 + g);         // edges i+8 .. i+15
        float4 v0 = __ldg(T4 + (size_t)s0 * 4 + l4);
        float4 v1 = __ldg(T4 + (size_t)s1 * 4 + l4);
        acc4(aA, v0);
        acc4(aB, v1);
    }
    for (; i < end; i += 8) {
        int e = i + g;
        if (e < end) {
            int s = __ldg(csr + e);
            float4 v = __ldg(T4 + (size_t)s * 4 + l4);
            acc4(aA, v);
        }
    }
    acc4(aA, aB);
#pragma unroll
    for (int off = 4; off <= 16; off <<= 1) {
        aA.x += __shfl_down_sync(0xffffffffu, aA.x, off);
        aA.y += __shfl_down_sync(0xffffffffu, aA.y, off);
        aA.z += __shfl_down_sync(0xffffffffu, aA.z, off);
        aA.w += __shfl_down_sync(0xffffffffu, aA.w, off);
    }

    // lanes 0-3 hold the full column-chunk sums; combine + fused head
    float partial = 0.0f;
    if (lane < 4) {
        float4 u = __ldg(reinterpret_cast<const float4*>(U) + (size_t)node * 4 + l4);
        float4 h;
        h.x = fmaxf(fmaf(aA.x, iv, u.x), 0.0f);
        h.y = fmaxf(fmaf(aA.y, iv, u.y), 0.0f);
        h.z = fmaxf(fmaf(aA.z, iv, u.z), 0.0f);
        h.w = fmaxf(fmaf(aA.w, iv, u.w), 0.0f);
        float4 w = __ldg(reinterpret_cast<const float4*>(Wc) + l4);
        partial = h.x * w.x + h.y * w.y + h.z * w.z + h.w * w.w;
    }
    partial += __shfl_down_sync(0xffffffffu, partial, 2);
    partial += __shfl_down_sync(0xffffffffu, partial, 1);
    if (lane == 0) out[node] = partial + __ldg(bc);
}

// ---------------------------------------------------------------------------

template <int DIN, int DOUT>
static void launch_gemm(const float* X, const float* Wl, const float* Wr,
                        const float* B, float* T, float* U, int n) {
    constexpr int BT = 8 * 8 * (32 / (DOUT / 2));
    constexpr int SMEM = (DIN * 2 * DOUT + BT * (DIN + 4)) * (int)sizeof(float);
    int ntiles = cdiv(n, BT);
    cudaFuncSetAttribute(gemm_kernel<DIN, DOUT>,
                         cudaFuncAttributeMaxDynamicSharedMemorySize, SMEM);
    int grid = ntiles < 592 ? ntiles : 592;
    gemm_kernel<DIN, DOUT><<<grid, 256, SMEM>>>(X, Wl, Wr, B, T, U, n, ntiles);
}

extern "C" void kernel_launch(void* const* d_in, const int* in_sizes, int n_in,
                              void* d_out, int out_size) {
    const float* x   = (const float*)d_in[0];
    const int* eidx  = (const int*)d_in[1];
    const float* Wl0 = (const float*)d_in[2];
    const float* Wr0 = (const float*)d_in[3];
    const float* b0  = (const float*)d_in[4];
    const float* Wl1 = (const float*)d_in[5];
    const float* Wr1 = (const float*)d_in[6];
    const float* b1  = (const float*)d_in[7];
    const float* Wl2 = (const float*)d_in[8];
    const float* Wr2 = (const float*)d_in[9];
    const float* b2  = (const float*)d_in[10];
    const float* Wc  = (const float*)d_in[11];
    const float* bc  = (const float*)d_in[12];
    float* out = (float*)d_out;

    const int n = in_sizes[0] / 64;        // 100000
    const int e = in_sizes[1] / 2;         // 3200000
    const int* src = eidx;
    const int* dst = eidx + e;

    float *t, *u, *h, *inv;
    int *cnt, *rs, *cur, *csr, *bsum;
    cudaGetSymbolAddress((void**)&t, g_t);
    cudaGetSymbolAddress((void**)&u, g_u);
    cudaGetSymbolAddress((void**)&h, g_h);
    cudaGetSymbolAddress((void**)&inv, g_inv);
    cudaGetSymbolAddress((void**)&cnt, g_cnt);
    cudaGetSymbolAddress((void**)&rs, g_rs);
    cudaGetSymbolAddress((void**)&cur, g_cur);
    cudaGetSymbolAddress((void**)&csr, g_csr);
    cudaGetSymbolAddress((void**)&bsum, g_bsum);

    const int nb = cdiv(n, 256);

    // --- CSR + inv_deg (built once, reused 3x) ---
    zero_cnt_kernel<<<cdiv(n, 256), 256>>>(cnt, n);
    hist_kernel<<<cdiv(e, 256), 256>>>(dst, cnt, e);
    scan1_kernel<<<nb, 256>>>(cnt, rs, bsum, n);
    scan2_kernel<<<1, 512>>>(bsum, nb);
    scan3_kernel<<<nb, 256>>>(cnt, rs, cur, inv, bsum, n);
    fill_kernel<<<cdiv(e, 256), 256>>>(src, dst, cur, csr, e);

    // --- layer 0: 64 -> 64 ---
    launch_gemm<64, 64>(x, Wl0, Wr0, b0, t, u, n);
    gather64_kernel<<<cdiv((long long)n * 32, 256), 256>>>(rs, csr, t, u, inv, h, n);

    // --- layer 1: 64 -> 32 ---
    launch_gemm<64, 32>(h, Wl1, Wr1, b1, t, u, n);
    gather32_kernel<<<cdiv((long long)n * 32, 256), 256>>>(rs, csr, t, u, inv, h, n);

    // --- layer 2: 32 -> 16, fused with 16 -> 1 head ---
    launch_gemm<32, 16>(h, Wl2, Wr2, b2, t, u, n);
    gather16_head_kernel<<<cdiv((long long)n * 32, 256), 256>>>(rs, csr, t, u, inv,
                                                                Wc, bc, out, n);
}